// round 6
// baseline (speedup 1.0000x reference)
#include <cuda_runtime.h>
#include <cuda_fp16.h>
#include <math.h>
#include <stdint.h>

// MoELayer_47193100648722: N=8192 tokens, D=2048, H=2048, E=8, top-2, fp32.
#define NTOK 8192
#define DDIM 2048
#define HDIM 2048
#define NEXP 8

#define BM 256
#define BN 128
#define BK 64          // halves per k-iter => 128B rows
#define STAGES 3
#define NITER (DDIM / BK)   // 32

// ---------------------------------------------------------------------------
// Device scratch (no cudaMalloc allowed)
// ---------------------------------------------------------------------------
__device__ int    g_cnt[NEXP];
__device__ int    g_tok[NEXP * NTOK];        // packed: token*2 + slot
__device__ float  g_wt [NEXP * NTOK];
__device__ __half g_We_h[(size_t)NEXP * DDIM * HDIM]; // [e][h][d], fp16
__device__ __half g_x_h [(size_t)NTOK * DDIM];        // x, fp16
__device__ float  g_part[2ull * NTOK * HDIM];         // per-slot partials

// ---------------------------------------------------------------------------
// Helpers (base sm_103-safe)
// ---------------------------------------------------------------------------
__device__ __forceinline__ uint32_t smem_u32(const void* p) {
    return (uint32_t)__cvta_generic_to_shared(p);
}
__device__ __forceinline__ void cp16(uint32_t dst, const void* src) {
    asm volatile("cp.async.cg.shared.global [%0], [%1], 16;" :: "r"(dst), "l"(src));
}
#define CP_COMMIT() asm volatile("cp.async.commit_group;" ::: "memory")
#define SWZ(o) ((o) ^ (((o) >> 3) & 0x70))

#define LDSM4(R0, R1, R2, R3, addr)                                          \
    asm volatile("ldmatrix.sync.aligned.m8n8.x4.shared.b16 {%0,%1,%2,%3}, [%4];" \
                 : "=r"(R0), "=r"(R1), "=r"(R2), "=r"(R3) : "r"(addr))

#define MMA_F16(d, a, b)                                                     \
    asm volatile("mma.sync.aligned.m16n8k16.row.col.f32.f16.f16.f32 "        \
                 "{%0,%1,%2,%3}, {%4,%5,%6,%7}, {%8,%9}, {%0,%1,%2,%3};"     \
                 : "+f"((d)[0]), "+f"((d)[1]), "+f"((d)[2]), "+f"((d)[3])    \
                 : "r"((a)[0]), "r"((a)[1]), "r"((a)[2]), "r"((a)[3]),       \
                   "r"((b)[0]), "r"((b)[1]))

// ---------------------------------------------------------------------------
// Kernel 0: zero counters
// ---------------------------------------------------------------------------
__global__ void k_zero_cnt() {
    if (threadIdx.x < NEXP) g_cnt[threadIdx.x] = 0;
}

// ---------------------------------------------------------------------------
// Kernel T: transpose We[e][d][h] -> g_We_h[e][h][d] (fp16), half2 stores.
// grid (D/64, H/32, E), block (32, 8)
// ---------------------------------------------------------------------------
__global__ void k_transpose(const float* __restrict__ We) {
    __shared__ float tile[64][33];
    int e = blockIdx.z;
    int d0 = blockIdx.x * 64, h0 = blockIdx.y * 32;
    const float* src = We + (size_t)e * DDIM * HDIM;
    __half* dst = g_We_h + (size_t)e * HDIM * DDIM;
    int tx = threadIdx.x, ty = threadIdx.y;
#pragma unroll
    for (int j = 0; j < 8; j++)
        tile[ty + j * 8][tx] = src[(size_t)(d0 + ty + j * 8) * HDIM + h0 + tx];
    __syncthreads();
#pragma unroll
    for (int j = 0; j < 4; j++) {
        int hl = ty + j * 8;
        __half2 v = __floats2half2_rn(tile[2 * tx][hl], tile[2 * tx + 1][hl]);
        *(__half2*)(dst + (size_t)(h0 + hl) * DDIM + d0 + 2 * tx) = v;
    }
}

// ---------------------------------------------------------------------------
// Kernel 1: gating + x->fp16 conversion, fused. One warp per token.
//   float4 loads (512B/warp/iter), logits for 8 experts, writes fp16 row,
//   softmax, top-2, appends (token*2+slot, weight) to per-expert lists.
// ---------------------------------------------------------------------------
__global__ void k_gate(const float* __restrict__ x,
                       const float* __restrict__ Wg,
                       const float* __restrict__ bg) {
    int gwarp = (blockIdx.x * blockDim.x + threadIdx.x) >> 5;
    int lane  = threadIdx.x & 31;
    if (gwarp >= NTOK) return;

    const float4* xr = (const float4*)(x + (size_t)gwarp * DDIM);
    __half2* xo = (__half2*)(g_x_h + (size_t)gwarp * DDIM);

    float acc[NEXP];
#pragma unroll
    for (int e = 0; e < NEXP; e++) acc[e] = 0.f;

#pragma unroll 4
    for (int it = 0; it < DDIM / 128; it++) {          // 16 iters
        int d4 = it * 32 + lane;                        // float4 index
        float4 v = xr[d4];
        // emit fp16 copy
        xo[2 * d4]     = __floats2half2_rn(v.x, v.y);
        xo[2 * d4 + 1] = __floats2half2_rn(v.z, v.w);
        // accumulate logits: rows 4*d4 .. 4*d4+3 of Wg
        const float4* wr = (const float4*)(Wg + (size_t)d4 * 4 * NEXP);
        float xs[4] = {v.x, v.y, v.z, v.w};
#pragma unroll
        for (int r = 0; r < 4; r++) {
            float4 w0 = wr[2 * r];
            float4 w1 = wr[2 * r + 1];
            acc[0] += xs[r] * w0.x;  acc[1] += xs[r] * w0.y;
            acc[2] += xs[r] * w0.z;  acc[3] += xs[r] * w0.w;
            acc[4] += xs[r] * w1.x;  acc[5] += xs[r] * w1.y;
            acc[6] += xs[r] * w1.z;  acc[7] += xs[r] * w1.w;
        }
    }
#pragma unroll
    for (int e = 0; e < NEXP; e++) {
#pragma unroll
        for (int o = 16; o > 0; o >>= 1)
            acc[e] += __shfl_xor_sync(0xFFFFFFFFu, acc[e], o);
    }
    if (lane == 0) {
#pragma unroll
        for (int e = 0; e < NEXP; e++) acc[e] += bg[e];
        float m1 = acc[0]; int i1 = 0;
#pragma unroll
        for (int e = 1; e < NEXP; e++)
            if (acc[e] > m1) { m1 = acc[e]; i1 = e; }
        float m2 = -INFINITY; int i2 = 0;
#pragma unroll
        for (int e = 0; e < NEXP; e++) {
            if (e == i1) continue;
            if (acc[e] > m2) { m2 = acc[e]; i2 = e; }
        }
        float s = 0.f;
#pragma unroll
        for (int e = 0; e < NEXP; e++) s += __expf(acc[e] - m1);
        float inv = 1.f / s;
        float w1v = inv;
        float w2v = __expf(m2 - m1) * inv;

        int p1 = atomicAdd(&g_cnt[i1], 1);
        g_tok[i1 * NTOK + p1] = gwarp * 2;       // slot 0
        g_wt [i1 * NTOK + p1] = w1v;
        int p2 = atomicAdd(&g_cnt[i2], 1);
        g_tok[i2 * NTOK + p2] = gwarp * 2 + 1;   // slot 1
        g_wt [i2 * NTOK + p2] = w2v;
    }
}

// ---------------------------------------------------------------------------
// Kernel 2: grouped expert GEMM — mma.sync fp16 (m16n8k16), 3-stage cp.async.
//   C[256 tok x 128 h] per CTA. 16 warps in 4(m) x 4(n), each 64x32.
//   Epilogue: plain v2 stores into per-slot partial buffers (no atomics).
// SMEM: 3 stages x (A 32KB + B 16KB) = 144KB, then s_tok/s_w/s_be.
// ---------------------------------------------------------------------------
#define SM_STAGE 49152
#define SM_TOK   (STAGES * SM_STAGE)          // 147456
#define SM_W     (SM_TOK + 1024)
#define SM_BE    (SM_W + 1024)
#define SMEM_BYTES (SM_BE + 512)

__global__ void __launch_bounds__(512, 1)
k_moe_gemm(const float* __restrict__ be) {
    extern __shared__ char dsm[];
    const int e   = blockIdx.z;
    const int cnt = g_cnt[e];
    const int m0  = blockIdx.y * BM;
    if (m0 >= cnt) return;
    const int n0  = blockIdx.x * BN;
    const int tid = threadIdx.x;
    const uint32_t sb = smem_u32(dsm);

    int*   s_tok = (int*)(dsm + SM_TOK);
    float* s_w   = (float*)(dsm + SM_W);
    float* s_be  = (float*)(dsm + SM_BE);

    if (tid < BM) {
        int r = m0 + tid;
        int t; float w;
        if (r < cnt) { t = g_tok[e * NTOK + r]; w = g_wt[e * NTOK + r]; }
        else         { t = -1; w = 0.f; }
        s_tok[tid] = t; s_w[tid] = w;
    }
    if (tid < BN) s_be[tid] = be[e * HDIM + n0 + tid];
    __syncthreads();

    // Per-thread cp.async sources + swizzled dsts. 128B rows (BK=64 halves).
    const char* gA[4]; const char* gB[2];
    uint32_t dA[4], dB[2];
    {
        const int c8 = (tid & 7) * 16;
#pragma unroll
        for (int j = 0; j < 4; j++) {                  // A: 256 rows
            int row = (tid + j * 512) >> 3;            // 0..255
            int pk = s_tok[row];
            int t = (pk < 0) ? 0 : (pk >> 1);
            gA[j] = (const char*)(g_x_h + (size_t)t * DDIM) + c8;
            dA[j] = sb + SWZ(row * 128 + c8);
        }
#pragma unroll
        for (int j = 0; j < 2; j++) {                  // B: 128 rows
            int row = (tid + j * 512) >> 3;            // 0..127
            gB[j] = (const char*)(g_We_h + ((size_t)e * HDIM + n0 + row) * DDIM) + c8;
            dB[j] = sb + 32768 + SWZ(row * 128 + c8);
        }
    }

    // ldmatrix raw offsets + constant per-thread swizzle XOR.
    const int lane = tid & 31, warp = tid >> 5;
    const int wm = (warp & 3) * 64, wn = (warp >> 2) * 32;
    const int lr = lane & 7, q = lane >> 3;
    const uint32_t aRaw = (uint32_t)(wm + lr + 8 * (q & 1)) * 128 + 16 * (q >> 1);
    const uint32_t aX   = (aRaw >> 3) & 0x70;
    const uint32_t bRaw = (uint32_t)(wn + lr + 8 * (q >> 1)) * 128 + 16 * (q & 1);
    const uint32_t bX   = (bRaw >> 3) & 0x70;

    float acc[4][4][4];
#pragma unroll
    for (int i = 0; i < 4; i++)
#pragma unroll
        for (int j = 0; j < 4; j++)
#pragma unroll
            for (int c = 0; c < 4; c++) acc[i][j][c] = 0.f;

#pragma unroll
    for (int s = 0; s < STAGES - 1; s++) {
        const int off = s * 128;                 // BK*2 bytes per k-iter
        const uint32_t so = s * SM_STAGE;
#pragma unroll
        for (int j = 0; j < 4; j++) cp16(dA[j] + so, gA[j] + off);
#pragma unroll
        for (int j = 0; j < 2; j++) cp16(dB[j] + so, gB[j] + off);
        CP_COMMIT();
    }

    for (int it = 0; it < NITER; ++it) {
        if (it + STAGES - 1 < NITER)
            asm volatile("cp.async.wait_group %0;" :: "n"(STAGES - 2) : "memory");
        else
            asm volatile("cp.async.wait_group 0;" ::: "memory");
        __syncthreads();

        const int nxt = it + STAGES - 1;
        if (nxt < NITER) {
            const int off = nxt * 128;
            const uint32_t so = (nxt % STAGES) * SM_STAGE;
#pragma unroll
            for (int j = 0; j < 4; j++) cp16(dA[j] + so, gA[j] + off);
#pragma unroll
            for (int j = 0; j < 2; j++) cp16(dB[j] + so, gB[j] + off);
            CP_COMMIT();
        }

        const uint32_t st = sb + (it % STAGES) * SM_STAGE;
#pragma unroll
        for (int kk = 0; kk < 4; kk++) {      // 4 x k16 per BK=64
            uint32_t a[4][4], b[4][2];
#pragma unroll
            for (int i = 0; i < 4; i++)
                LDSM4(a[i][0], a[i][1], a[i][2], a[i][3],
                      st + ((aRaw + i * 2048 + kk * 32) ^ aX));
#pragma unroll
            for (int jj = 0; jj < 2; jj++) {
                uint32_t r0, r1, r2, r3;
                LDSM4(r0, r1, r2, r3,
                      st + 32768u + ((bRaw + jj * 2048 + kk * 32) ^ bX));
                b[2 * jj][0] = r0; b[2 * jj][1] = r1;
                b[2 * jj + 1][0] = r2; b[2 * jj + 1][1] = r3;
            }
#pragma unroll
            for (int i = 0; i < 4; i++)
#pragma unroll
                for (int j = 0; j < 4; j++)
                    MMA_F16(acc[i][j], a[i], b[j]);
        }
    }

    // Epilogue: plain float2 stores into per-slot partial buffer.
    const int rr = lane >> 2;
    const int cc = (lane & 3) * 2;
#pragma unroll
    for (int i = 0; i < 4; i++) {
        const int m1 = wm + 16 * i + rr;
        const int m2 = m1 + 8;
        const int pk1 = s_tok[m1], pk2 = s_tok[m2];
        const float w1 = s_w[m1], w2 = s_w[m2];
        float* o1 = g_part + ((size_t)(pk1 & 1) * NTOK + (pk1 >> 1)) * HDIM + n0;
        float* o2 = g_part + ((size_t)(pk2 & 1) * NTOK + (pk2 >> 1)) * HDIM + n0;
#pragma unroll
        for (int j = 0; j < 4; j++) {
            const int n = wn + 8 * j + cc;
            if (pk1 >= 0) {
                float2 v = make_float2(w1 * (acc[i][j][0] + s_be[n]),
                                       w1 * (acc[i][j][1] + s_be[n + 1]));
                *(float2*)(o1 + n) = v;
            }
            if (pk2 >= 0) {
                float2 v = make_float2(w2 * (acc[i][j][2] + s_be[n]),
                                       w2 * (acc[i][j][3] + s_be[n + 1]));
                *(float2*)(o2 + n) = v;
            }
        }
    }
}

// ---------------------------------------------------------------------------
// Kernel 3: combine — out = part[slot0] + part[slot1]
// ---------------------------------------------------------------------------
__global__ void k_combine(float4* __restrict__ out, int n4) {
    int i = blockIdx.x * blockDim.x + threadIdx.x;
    if (i < n4) {
        float4 a = ((const float4*)g_part)[i];
        float4 b = ((const float4*)g_part)[(size_t)NTOK * HDIM / 4 + i];
        out[i] = make_float4(a.x + b.x, a.y + b.y, a.z + b.z, a.w + b.w);
    }
}

// ---------------------------------------------------------------------------
// Launch
// ---------------------------------------------------------------------------
extern "C" void kernel_launch(void* const* d_in, const int* in_sizes, int n_in,
                              void* d_out, int out_size) {
    const float* x  = (const float*)d_in[0];   // [N, D]
    const float* Wg = (const float*)d_in[1];   // [D, E]
    const float* bg = (const float*)d_in[2];   // [E]
    const float* We = (const float*)d_in[3];   // [E, D, H]
    const float* be = (const float*)d_in[4];   // [E, H]
    float* out = (float*)d_out;                // [N, H]
    (void)in_sizes; (void)n_in;

    cudaFuncSetAttribute(k_moe_gemm,
                         cudaFuncAttributeMaxDynamicSharedMemorySize, SMEM_BYTES);

    // 0) reset counters
    k_zero_cnt<<<1, 32>>>();

    // T) transpose + convert expert weights -> fp16 [e][h][d]
    {
        dim3 g(DDIM / 64, HDIM / 32, NEXP);
        dim3 b(32, 8);
        k_transpose<<<g, b>>>(We);
    }

    // 1) gating + x->fp16 (fused)
    k_gate<<<NTOK / 8, 256>>>(x, Wg, bg);

    // 2) grouped expert GEMM (mma.sync fp16, BM=256)
    {
        dim3 grid(HDIM / BN, NTOK / BM, NEXP);
        k_moe_gemm<<<grid, 512, SMEM_BYTES>>>(be);
    }

    // 3) combine slots
    {
        int n4 = NTOK * HDIM / 4;
        k_combine<<<(n4 + 255) / 256, 256>>>((float4*)out, n4);
    }
}

// round 7
// speedup vs baseline: 1.1098x; 1.1098x over previous
#include <cuda_runtime.h>
#include <cuda_fp16.h>
#include <math.h>
#include <stdint.h>

// MoELayer_47193100648722: N=8192 tokens, D=2048, H=2048, E=8, top-2, fp32.
#define NTOK 8192
#define DDIM 2048
#define HDIM 2048
#define NEXP 8

#define BM 128
#define BN 128
#define BK 64          // halves per k-iter => 128B rows
#define STAGES 3
#define NITER (DDIM / BK)   // 32

// ---------------------------------------------------------------------------
// Device scratch (no cudaMalloc allowed)
// ---------------------------------------------------------------------------
__device__ int    g_cnt[NEXP];
__device__ int    g_tok[NEXP * NTOK];        // packed: token*2 + slot
__device__ float  g_wt [NEXP * NTOK];
__device__ __half g_We_h[(size_t)NEXP * DDIM * HDIM]; // [e][h][d], fp16
__device__ __half g_x_h [(size_t)NTOK * DDIM];        // x, fp16
__device__ float  g_part[2ull * NTOK * HDIM];         // per-slot partials

// ---------------------------------------------------------------------------
// Helpers (base sm_103-safe)
// ---------------------------------------------------------------------------
__device__ __forceinline__ uint32_t smem_u32(const void* p) {
    return (uint32_t)__cvta_generic_to_shared(p);
}
__device__ __forceinline__ void cp16(uint32_t dst, const void* src) {
    asm volatile("cp.async.cg.shared.global [%0], [%1], 16;" :: "r"(dst), "l"(src));
}
#define CP_COMMIT() asm volatile("cp.async.commit_group;" ::: "memory")
#define SWZ(o) ((o) ^ (((o) >> 3) & 0x70))

#define LDSM4(R0, R1, R2, R3, addr)                                          \
    asm volatile("ldmatrix.sync.aligned.m8n8.x4.shared.b16 {%0,%1,%2,%3}, [%4];" \
                 : "=r"(R0), "=r"(R1), "=r"(R2), "=r"(R3) : "r"(addr))

#define MMA_F16(d, a, b)                                                     \
    asm volatile("mma.sync.aligned.m16n8k16.row.col.f32.f16.f16.f32 "        \
                 "{%0,%1,%2,%3}, {%4,%5,%6,%7}, {%8,%9}, {%0,%1,%2,%3};"     \
                 : "+f"((d)[0]), "+f"((d)[1]), "+f"((d)[2]), "+f"((d)[3])    \
                 : "r"((a)[0]), "r"((a)[1]), "r"((a)[2]), "r"((a)[3]),       \
                   "r"((b)[0]), "r"((b)[1]))

// ---------------------------------------------------------------------------
// Kernel 0: zero counters
// ---------------------------------------------------------------------------
__global__ void k_zero_cnt() {
    if (threadIdx.x < NEXP) g_cnt[threadIdx.x] = 0;
}

// ---------------------------------------------------------------------------
// Kernel T: transpose We[e][d][h] -> g_We_h[e][h][d] (fp16).
// 64(d) x 64(h) tiles; float2 loads, half2 stores. grid (D/64, H/64, E),
// block (32, 8) = 256 threads.
// ---------------------------------------------------------------------------
__global__ void k_transpose(const float* __restrict__ We) {
    __shared__ float tile[64][65];
    int e = blockIdx.z;
    int d0 = blockIdx.x * 64, h0 = blockIdx.y * 64;
    const float* src = We + (size_t)e * DDIM * HDIM;
    __half* dst = g_We_h + (size_t)e * HDIM * DDIM;
    int tx = threadIdx.x, ty = threadIdx.y;
    // Load: each thread float2 along h; 32 threads cover 64 h. 8 ty x 8 rows.
#pragma unroll
    for (int j = 0; j < 8; j++) {
        int d = ty + j * 8;
        float2 v = *(const float2*)(src + (size_t)(d0 + d) * HDIM + h0 + 2 * tx);
        tile[d][2 * tx]     = v.x;
        tile[d][2 * tx + 1] = v.y;
    }
    __syncthreads();
    // Store: half2 along d (2 consecutive d from tile rows), 32 tx cover 64 d.
#pragma unroll
    for (int j = 0; j < 8; j++) {
        int h = ty + j * 8;
        __half2 v = __floats2half2_rn(tile[2 * tx][h], tile[2 * tx + 1][h]);
        *(__half2*)(dst + (size_t)(h0 + h) * DDIM + d0 + 2 * tx) = v;
    }
}

// ---------------------------------------------------------------------------
// Kernel 1: gating + x->fp16 conversion, fused. One warp per token.
// ---------------------------------------------------------------------------
__global__ void k_gate(const float* __restrict__ x,
                       const float* __restrict__ Wg,
                       const float* __restrict__ bg) {
    int gwarp = (blockIdx.x * blockDim.x + threadIdx.x) >> 5;
    int lane  = threadIdx.x & 31;
    if (gwarp >= NTOK) return;

    const float4* xr = (const float4*)(x + (size_t)gwarp * DDIM);
    __half2* xo = (__half2*)(g_x_h + (size_t)gwarp * DDIM);

    float acc[NEXP];
#pragma unroll
    for (int e = 0; e < NEXP; e++) acc[e] = 0.f;

#pragma unroll 4
    for (int it = 0; it < DDIM / 128; it++) {          // 16 iters
        int d4 = it * 32 + lane;
        float4 v = xr[d4];
        xo[2 * d4]     = __floats2half2_rn(v.x, v.y);
        xo[2 * d4 + 1] = __floats2half2_rn(v.z, v.w);
        const float4* wr = (const float4*)(Wg + (size_t)d4 * 4 * NEXP);
        float xs[4] = {v.x, v.y, v.z, v.w};
#pragma unroll
        for (int r = 0; r < 4; r++) {
            float4 w0 = wr[2 * r];
            float4 w1 = wr[2 * r + 1];
            acc[0] += xs[r] * w0.x;  acc[1] += xs[r] * w0.y;
            acc[2] += xs[r] * w0.z;  acc[3] += xs[r] * w0.w;
            acc[4] += xs[r] * w1.x;  acc[5] += xs[r] * w1.y;
            acc[6] += xs[r] * w1.z;  acc[7] += xs[r] * w1.w;
        }
    }
#pragma unroll
    for (int e = 0; e < NEXP; e++) {
#pragma unroll
        for (int o = 16; o > 0; o >>= 1)
            acc[e] += __shfl_xor_sync(0xFFFFFFFFu, acc[e], o);
    }
    if (lane == 0) {
#pragma unroll
        for (int e = 0; e < NEXP; e++) acc[e] += bg[e];
        float m1 = acc[0]; int i1 = 0;
#pragma unroll
        for (int e = 1; e < NEXP; e++)
            if (acc[e] > m1) { m1 = acc[e]; i1 = e; }
        float m2 = -INFINITY; int i2 = 0;
#pragma unroll
        for (int e = 0; e < NEXP; e++) {
            if (e == i1) continue;
            if (acc[e] > m2) { m2 = acc[e]; i2 = e; }
        }
        float s = 0.f;
#pragma unroll
        for (int e = 0; e < NEXP; e++) s += __expf(acc[e] - m1);
        float inv = 1.f / s;
        float w1v = inv;
        float w2v = __expf(m2 - m1) * inv;

        int p1 = atomicAdd(&g_cnt[i1], 1);
        g_tok[i1 * NTOK + p1] = gwarp * 2;       // slot 0
        g_wt [i1 * NTOK + p1] = w1v;
        int p2 = atomicAdd(&g_cnt[i2], 1);
        g_tok[i2 * NTOK + p2] = gwarp * 2 + 1;   // slot 1
        g_wt [i2 * NTOK + p2] = w2v;
    }
}

// ---------------------------------------------------------------------------
// Kernel 2: grouped expert GEMM — mma.sync fp16 (m16n8k16), 3-stage cp.async.
//   C[128 tok x 128 h] per CTA, 256 threads, 8 warps in 2(m) x 4(n), 64x32.
//   2 CTAs/SM (96KB smem, 128 regs) so barrier stalls overlap across CTAs.
//   Epilogue: plain v2 stores into per-slot partial buffers (no atomics).
// ---------------------------------------------------------------------------
#define SM_STAGE 32768
#define SM_TOK   (STAGES * SM_STAGE)          // 98304
#define SM_W     (SM_TOK + 512)
#define SM_BE    (SM_W + 512)
#define SMEM_BYTES (SM_BE + 512)

__global__ void __launch_bounds__(256, 2)
k_moe_gemm(const float* __restrict__ be) {
    extern __shared__ char dsm[];
    const int e   = blockIdx.z;
    const int cnt = g_cnt[e];
    const int m0  = blockIdx.y * BM;
    if (m0 >= cnt) return;
    const int n0  = blockIdx.x * BN;
    const int tid = threadIdx.x;
    const uint32_t sb = smem_u32(dsm);

    int*   s_tok = (int*)(dsm + SM_TOK);
    float* s_w   = (float*)(dsm + SM_W);
    float* s_be  = (float*)(dsm + SM_BE);

    if (tid < BM) {
        int r = m0 + tid;
        int t; float w;
        if (r < cnt) { t = g_tok[e * NTOK + r]; w = g_wt[e * NTOK + r]; }
        else         { t = -1; w = 0.f; }
        s_tok[tid] = t; s_w[tid] = w;
        s_be[tid]  = be[e * HDIM + n0 + tid];
    }
    __syncthreads();

    // Per-thread cp.async sources + swizzled dsts. 128B rows (BK=64 halves).
    const char* gA[4]; const char* gB[4];
    uint32_t dA[4], dB[4];
    {
        const int c8 = (tid & 7) * 16;
#pragma unroll
        for (int j = 0; j < 4; j++) {
            int row = (tid + j * 256) >> 3;   // 0..127
            int pk = s_tok[row];
            int t = (pk < 0) ? 0 : (pk >> 1);
            gA[j] = (const char*)(g_x_h + (size_t)t * DDIM) + c8;
            dA[j] = sb + SWZ(row * 128 + c8);
            gB[j] = (const char*)(g_We_h + ((size_t)e * HDIM + n0 + row) * DDIM) + c8;
            dB[j] = sb + 16384 + SWZ(row * 128 + c8);
        }
    }

    // ldmatrix raw offsets + constant per-thread swizzle XOR (invariant under
    // +i*2048 and +kk*32).
    const int lane = tid & 31, warp = tid >> 5;
    const int wm = (warp & 1) * 64, wn = (warp >> 1) * 32;
    const int lr = lane & 7, q = lane >> 3;
    const uint32_t aRaw = (uint32_t)(wm + lr + 8 * (q & 1)) * 128 + 16 * (q >> 1);
    const uint32_t aX   = (aRaw >> 3) & 0x70;
    const uint32_t bRaw = (uint32_t)(wn + lr + 8 * (q >> 1)) * 128 + 16 * (q & 1);
    const uint32_t bX   = (bRaw >> 3) & 0x70;

    float acc[4][4][4];
#pragma unroll
    for (int i = 0; i < 4; i++)
#pragma unroll
        for (int j = 0; j < 4; j++)
#pragma unroll
            for (int c = 0; c < 4; c++) acc[i][j][c] = 0.f;

#pragma unroll
    for (int s = 0; s < STAGES - 1; s++) {
        const int off = s * 128;                 // BK*2 bytes per k-iter
        const uint32_t so = s * SM_STAGE;
#pragma unroll
        for (int j = 0; j < 4; j++) cp16(dA[j] + so, gA[j] + off);
#pragma unroll
        for (int j = 0; j < 4; j++) cp16(dB[j] + so, gB[j] + off);
        CP_COMMIT();
    }

    for (int it = 0; it < NITER; ++it) {
        if (it + STAGES - 1 < NITER)
            asm volatile("cp.async.wait_group %0;" :: "n"(STAGES - 2) : "memory");
        else
            asm volatile("cp.async.wait_group 0;" ::: "memory");
        __syncthreads();

        const int nxt = it + STAGES - 1;
        if (nxt < NITER) {
            const int off = nxt * 128;
            const uint32_t so = (nxt % STAGES) * SM_STAGE;
#pragma unroll
            for (int j = 0; j < 4; j++) cp16(dA[j] + so, gA[j] + off);
#pragma unroll
            for (int j = 0; j < 4; j++) cp16(dB[j] + so, gB[j] + off);
            CP_COMMIT();
        }

        const uint32_t st = sb + (it % STAGES) * SM_STAGE;
#pragma unroll
        for (int kk = 0; kk < 4; kk++) {      // 4 x k16 per BK=64
            uint32_t a[4][4], b[4][2];
#pragma unroll
            for (int i = 0; i < 4; i++)
                LDSM4(a[i][0], a[i][1], a[i][2], a[i][3],
                      st + ((aRaw + i * 2048 + kk * 32) ^ aX));
#pragma unroll
            for (int jj = 0; jj < 2; jj++) {
                uint32_t r0, r1, r2, r3;
                LDSM4(r0, r1, r2, r3,
                      st + 16384u + ((bRaw + jj * 2048 + kk * 32) ^ bX));
                b[2 * jj][0] = r0; b[2 * jj][1] = r1;
                b[2 * jj + 1][0] = r2; b[2 * jj + 1][1] = r3;
            }
#pragma unroll
            for (int i = 0; i < 4; i++)
#pragma unroll
                for (int j = 0; j < 4; j++)
                    MMA_F16(acc[i][j], a[i], b[j]);
        }
    }

    // Epilogue: plain float2 stores into per-slot partial buffer.
    const int rr = lane >> 2;
    const int cc = (lane & 3) * 2;
#pragma unroll
    for (int i = 0; i < 4; i++) {
        const int m1 = wm + 16 * i + rr;
        const int m2 = m1 + 8;
        const int pk1 = s_tok[m1], pk2 = s_tok[m2];
        const float w1 = s_w[m1], w2 = s_w[m2];
        float* o1 = g_part + ((size_t)(pk1 & 1) * NTOK + (pk1 >> 1)) * HDIM + n0;
        float* o2 = g_part + ((size_t)(pk2 & 1) * NTOK + (pk2 >> 1)) * HDIM + n0;
#pragma unroll
        for (int j = 0; j < 4; j++) {
            const int n = wn + 8 * j + cc;
            if (pk1 >= 0) {
                float2 v = make_float2(w1 * (acc[i][j][0] + s_be[n]),
                                       w1 * (acc[i][j][1] + s_be[n + 1]));
                *(float2*)(o1 + n) = v;
            }
            if (pk2 >= 0) {
                float2 v = make_float2(w2 * (acc[i][j][2] + s_be[n]),
                                       w2 * (acc[i][j][3] + s_be[n + 1]));
                *(float2*)(o2 + n) = v;
            }
        }
    }
}

// ---------------------------------------------------------------------------
// Kernel 3: combine — out = part[slot0] + part[slot1]
// ---------------------------------------------------------------------------
__global__ void k_combine(float4* __restrict__ out, int n4) {
    int i = blockIdx.x * blockDim.x + threadIdx.x;
    if (i < n4) {
        float4 a = ((const float4*)g_part)[i];
        float4 b = ((const float4*)g_part)[(size_t)NTOK * HDIM / 4 + i];
        out[i] = make_float4(a.x + b.x, a.y + b.y, a.z + b.z, a.w + b.w);
    }
}

// ---------------------------------------------------------------------------
// Launch
// ---------------------------------------------------------------------------
extern "C" void kernel_launch(void* const* d_in, const int* in_sizes, int n_in,
                              void* d_out, int out_size) {
    const float* x  = (const float*)d_in[0];   // [N, D]
    const float* Wg = (const float*)d_in[1];   // [D, E]
    const float* bg = (const float*)d_in[2];   // [E]
    const float* We = (const float*)d_in[3];   // [E, D, H]
    const float* be = (const float*)d_in[4];   // [E, H]
    float* out = (float*)d_out;                // [N, H]
    (void)in_sizes; (void)n_in;

    cudaFuncSetAttribute(k_moe_gemm,
                         cudaFuncAttributeMaxDynamicSharedMemorySize, SMEM_BYTES);

    // 0) reset counters
    k_zero_cnt<<<1, 32>>>();

    // T) transpose + convert expert weights -> fp16 [e][h][d]
    {
        dim3 g(DDIM / 64, HDIM / 64, NEXP);
        dim3 b(32, 8);
        k_transpose<<<g, b>>>(We);
    }

    // 1) gating + x->fp16 (fused)
    k_gate<<<NTOK / 8, 256>>>(x, Wg, bg);

    // 2) grouped expert GEMM (mma.sync fp16, BM=128, 2 CTA/SM)
    {
        dim3 grid(HDIM / BN, NTOK / BM, NEXP);
        k_moe_gemm<<<grid, 256, SMEM_BYTES>>>(be);
    }

    // 3) combine slots
    {
        int n4 = NTOK * HDIM / 4;
        k_combine<<<(n4 + 255) / 256, 256>>>((float4*)out, n4);
    }
}

// round 9
// speedup vs baseline: 1.3483x; 1.2148x over previous
#include <cuda_runtime.h>
#include <cuda_fp16.h>
#include <math.h>
#include <stdint.h>

// MoELayer_47193100648722: N=8192 tokens, D=2048, H=2048, E=8, top-2, fp32.
#define NTOK 8192
#define DDIM 2048
#define HDIM 2048
#define NEXP 8

#define BM 128
#define BN 128
#define BK 64          // halves per k-iter => 128B rows
#define STAGES 3
#define NITER (DDIM / BK)   // 32

// ---------------------------------------------------------------------------
// Device scratch (no cudaMalloc allowed)
// ---------------------------------------------------------------------------
__device__ int    g_cnt[NEXP];
__device__ int    g_tok[NEXP * NTOK];        // packed: token*2 + slot
__device__ float  g_wt [NEXP * NTOK];
__device__ __half g_We_h[(size_t)NEXP * DDIM * HDIM]; // [e][h][d], fp16
__device__ __half g_x_h [(size_t)NTOK * DDIM];        // x, fp16
__device__ float  g_part[2ull * NTOK * HDIM];         // per-slot partials

// ---------------------------------------------------------------------------
// Helpers (base sm_103-safe)
// ---------------------------------------------------------------------------
__device__ __forceinline__ uint32_t smem_u32(const void* p) {
    return (uint32_t)__cvta_generic_to_shared(p);
}
__device__ __forceinline__ void cp16(uint32_t dst, const void* src) {
    asm volatile("cp.async.cg.shared.global [%0], [%1], 16;" :: "r"(dst), "l"(src));
}
#define CP_COMMIT() asm volatile("cp.async.commit_group;" ::: "memory")
#define SWZ(o) ((o) ^ (((o) >> 3) & 0x70))

#define LDSM4(R0, R1, R2, R3, addr)                                          \
    asm volatile("ldmatrix.sync.aligned.m8n8.x4.shared.b16 {%0,%1,%2,%3}, [%4];" \
                 : "=r"(R0), "=r"(R1), "=r"(R2), "=r"(R3) : "r"(addr))

#define MMA_F16(d, a, b)                                                     \
    asm volatile("mma.sync.aligned.m16n8k16.row.col.f32.f16.f16.f32 "        \
                 "{%0,%1,%2,%3}, {%4,%5,%6,%7}, {%8,%9}, {%0,%1,%2,%3};"     \
                 : "+f"((d)[0]), "+f"((d)[1]), "+f"((d)[2]), "+f"((d)[3])    \
                 : "r"((a)[0]), "r"((a)[1]), "r"((a)[2]), "r"((a)[3]),       \
                   "r"((b)[0]), "r"((b)[1]))

// ---------------------------------------------------------------------------
// Kernel 0: zero counters
// ---------------------------------------------------------------------------
__global__ void k_zero_cnt() {
    if (threadIdx.x < NEXP) g_cnt[threadIdx.x] = 0;
}

// ---------------------------------------------------------------------------
// Kernel T: transpose We[e][d][h] -> g_We_h[e][h][d] (fp16).
// 64(d) x 64(h) tiles; float2 loads, half2 stores.
// ---------------------------------------------------------------------------
__global__ void k_transpose(const float* __restrict__ We) {
    __shared__ float tile[64][65];
    int e = blockIdx.z;
    int d0 = blockIdx.x * 64, h0 = blockIdx.y * 64;
    const float* src = We + (size_t)e * DDIM * HDIM;
    __half* dst = g_We_h + (size_t)e * HDIM * DDIM;
    int tx = threadIdx.x, ty = threadIdx.y;
#pragma unroll
    for (int j = 0; j < 8; j++) {
        int d = ty + j * 8;
        float2 v = *(const float2*)(src + (size_t)(d0 + d) * HDIM + h0 + 2 * tx);
        tile[d][2 * tx]     = v.x;
        tile[d][2 * tx + 1] = v.y;
    }
    __syncthreads();
#pragma unroll
    for (int j = 0; j < 8; j++) {
        int h = ty + j * 8;
        __half2 v = __floats2half2_rn(tile[2 * tx][h], tile[2 * tx + 1][h]);
        *(__half2*)(dst + (size_t)(h0 + h) * DDIM + d0 + 2 * tx) = v;
    }
}

// ---------------------------------------------------------------------------
// Kernel 1: gating + x->fp16, fused, Wg resident in DYNAMIC SMEM (64KB).
//   256 threads = 8 warps; each warp processes 4 tokens concurrently so the
//   Wg smem reads (128B/lane/iter) amortize over 4 tokens. FFMA-bound.
//   grid = NTOK/32.
// ---------------------------------------------------------------------------
#define GATE_SMEM (DDIM * NEXP * 4)   // 65536 bytes

__global__ void __launch_bounds__(256, 2)
k_gate(const float* __restrict__ x,
       const float* __restrict__ Wg,
       const float* __restrict__ bg) {
    extern __shared__ float4 wg_s[];           // 64KB dynamic, [d*8+e]/4
    const int tid  = threadIdx.x;
    const int lane = tid & 31;
    const int warp = tid >> 5;

    // Cooperative Wg load: 4096 float4 / 256 threads = 16 each, coalesced.
#pragma unroll
    for (int i = 0; i < 16; i++)
        wg_s[tid + i * 256] = ((const float4*)Wg)[tid + i * 256];
    __syncthreads();

    const int t0 = blockIdx.x * 32 + warp * 4;   // 4 tokens per warp

    const float4* xr0 = (const float4*)(x + (size_t)t0 * DDIM);
    __half2*      xo0 = (__half2*)(g_x_h + (size_t)t0 * DDIM);

    float acc[4][NEXP];
#pragma unroll
    for (int tt = 0; tt < 4; tt++)
#pragma unroll
        for (int e = 0; e < NEXP; e++) acc[tt][e] = 0.f;

    const int ls = lane & 7;

    for (int it = 0; it < 16; it++) {
        const int d4 = it * 32 + lane;           // this lane's float4 index

        // Wg fragment: rows 4*d4..4*d4+3, all 8 experts = 8 float4 = 128B.
        // Issue order XORed by (lane&7) so each instruction spreads banks.
        float4 w4[8];
#pragma unroll
        for (int s = 0; s < 8; s++) {
            int jj = s ^ ls;
            w4[jj] = wg_s[8 * d4 + jj];
        }

#pragma unroll
        for (int tt = 0; tt < 4; tt++) {
            float4 v = xr0[(size_t)tt * (DDIM / 4) + d4];
            xo0[(size_t)tt * (DDIM / 2) + 2 * d4]     = __floats2half2_rn(v.x, v.y);
            xo0[(size_t)tt * (DDIM / 2) + 2 * d4 + 1] = __floats2half2_rn(v.z, v.w);
            float xs[4] = {v.x, v.y, v.z, v.w};
#pragma unroll
            for (int dl = 0; dl < 4; dl++) {
                float4 wlo = w4[2 * dl];
                float4 whi = w4[2 * dl + 1];
                acc[tt][0] += xs[dl] * wlo.x;  acc[tt][1] += xs[dl] * wlo.y;
                acc[tt][2] += xs[dl] * wlo.z;  acc[tt][3] += xs[dl] * wlo.w;
                acc[tt][4] += xs[dl] * whi.x;  acc[tt][5] += xs[dl] * whi.y;
                acc[tt][6] += xs[dl] * whi.z;  acc[tt][7] += xs[dl] * whi.w;
            }
        }
    }

    // Warp reductions.
#pragma unroll
    for (int tt = 0; tt < 4; tt++)
#pragma unroll
        for (int e = 0; e < NEXP; e++) {
#pragma unroll
            for (int o = 16; o > 0; o >>= 1)
                acc[tt][e] += __shfl_xor_sync(0xFFFFFFFFu, acc[tt][e], o);
        }

    if (lane == 0) {
#pragma unroll
        for (int tt = 0; tt < 4; tt++) {
            float lg[NEXP];
#pragma unroll
            for (int e = 0; e < NEXP; e++) lg[e] = acc[tt][e] + bg[e];
            float m1 = lg[0]; int i1 = 0;
#pragma unroll
            for (int e = 1; e < NEXP; e++)
                if (lg[e] > m1) { m1 = lg[e]; i1 = e; }
            float m2 = -INFINITY; int i2 = 0;
#pragma unroll
            for (int e = 0; e < NEXP; e++) {
                if (e == i1) continue;
                if (lg[e] > m2) { m2 = lg[e]; i2 = e; }
            }
            float s = 0.f;
#pragma unroll
            for (int e = 0; e < NEXP; e++) s += __expf(lg[e] - m1);
            float inv = 1.f / s;
            float w1v = inv;
            float w2v = __expf(m2 - m1) * inv;

            int token = t0 + tt;
            int p1 = atomicAdd(&g_cnt[i1], 1);
            g_tok[i1 * NTOK + p1] = token * 2;       // slot 0
            g_wt [i1 * NTOK + p1] = w1v;
            int p2 = atomicAdd(&g_cnt[i2], 1);
            g_tok[i2 * NTOK + p2] = token * 2 + 1;   // slot 1
            g_wt [i2 * NTOK + p2] = w2v;
        }
    }
}

// ---------------------------------------------------------------------------
// Kernel 2: grouped expert GEMM — mma.sync fp16 (m16n8k16), 3-stage cp.async.
//   C[128 tok x 128 h] per CTA, 256 threads, 8 warps in 2(m) x 4(n), 64x32.
//   2 CTAs/SM. Epilogue: v2 stores into per-slot partial buffers (no atomics).
// ---------------------------------------------------------------------------
#define SM_STAGE 32768
#define SM_TOK   (STAGES * SM_STAGE)          // 98304
#define SM_W     (SM_TOK + 512)
#define SM_BE    (SM_W + 512)
#define SMEM_BYTES (SM_BE + 512)

__global__ void __launch_bounds__(256, 2)
k_moe_gemm(const float* __restrict__ be) {
    extern __shared__ char dsm[];
    const int e   = blockIdx.z;
    const int cnt = g_cnt[e];
    const int m0  = blockIdx.y * BM;
    if (m0 >= cnt) return;
    const int n0  = blockIdx.x * BN;
    const int tid = threadIdx.x;
    const uint32_t sb = smem_u32(dsm);

    int*   s_tok = (int*)(dsm + SM_TOK);
    float* s_w   = (float*)(dsm + SM_W);
    float* s_be  = (float*)(dsm + SM_BE);

    if (tid < BM) {
        int r = m0 + tid;
        int t; float w;
        if (r < cnt) { t = g_tok[e * NTOK + r]; w = g_wt[e * NTOK + r]; }
        else         { t = -1; w = 0.f; }
        s_tok[tid] = t; s_w[tid] = w;
        s_be[tid]  = be[e * HDIM + n0 + tid];
    }
    __syncthreads();

    const char* gA[4]; const char* gB[4];
    uint32_t dA[4], dB[4];
    {
        const int c8 = (tid & 7) * 16;
#pragma unroll
        for (int j = 0; j < 4; j++) {
            int row = (tid + j * 256) >> 3;   // 0..127
            int pk = s_tok[row];
            int t = (pk < 0) ? 0 : (pk >> 1);
            gA[j] = (const char*)(g_x_h + (size_t)t * DDIM) + c8;
            dA[j] = sb + SWZ(row * 128 + c8);
            gB[j] = (const char*)(g_We_h + ((size_t)e * HDIM + n0 + row) * DDIM) + c8;
            dB[j] = sb + 16384 + SWZ(row * 128 + c8);
        }
    }

    const int lane = tid & 31, warp = tid >> 5;
    const int wm = (warp & 1) * 64, wn = (warp >> 1) * 32;
    const int lr = lane & 7, q = lane >> 3;
    const uint32_t aRaw = (uint32_t)(wm + lr + 8 * (q & 1)) * 128 + 16 * (q >> 1);
    const uint32_t aX   = (aRaw >> 3) & 0x70;
    const uint32_t bRaw = (uint32_t)(wn + lr + 8 * (q >> 1)) * 128 + 16 * (q & 1);
    const uint32_t bX   = (bRaw >> 3) & 0x70;

    float acc[4][4][4];
#pragma unroll
    for (int i = 0; i < 4; i++)
#pragma unroll
        for (int j = 0; j < 4; j++)
#pragma unroll
            for (int c = 0; c < 4; c++) acc[i][j][c] = 0.f;

#pragma unroll
    for (int s = 0; s < STAGES - 1; s++) {
        const int off = s * 128;
        const uint32_t so = s * SM_STAGE;
#pragma unroll
        for (int j = 0; j < 4; j++) cp16(dA[j] + so, gA[j] + off);
#pragma unroll
        for (int j = 0; j < 4; j++) cp16(dB[j] + so, gB[j] + off);
        CP_COMMIT();
    }

    for (int it = 0; it < NITER; ++it) {
        if (it + STAGES - 1 < NITER)
            asm volatile("cp.async.wait_group %0;" :: "n"(STAGES - 2) : "memory");
        else
            asm volatile("cp.async.wait_group 0;" ::: "memory");
        __syncthreads();

        const int nxt = it + STAGES - 1;
        if (nxt < NITER) {
            const int off = nxt * 128;
            const uint32_t so = (nxt % STAGES) * SM_STAGE;
#pragma unroll
            for (int j = 0; j < 4; j++) cp16(dA[j] + so, gA[j] + off);
#pragma unroll
            for (int j = 0; j < 4; j++) cp16(dB[j] + so, gB[j] + off);
            CP_COMMIT();
        }

        const uint32_t st = sb + (it % STAGES) * SM_STAGE;
#pragma unroll
        for (int kk = 0; kk < 4; kk++) {
            uint32_t a[4][4], b[4][2];
#pragma unroll
            for (int i = 0; i < 4; i++)
                LDSM4(a[i][0], a[i][1], a[i][2], a[i][3],
                      st + ((aRaw + i * 2048 + kk * 32) ^ aX));
#pragma unroll
            for (int jj = 0; jj < 2; jj++) {
                uint32_t r0, r1, r2, r3;
                LDSM4(r0, r1, r2, r3,
                      st + 16384u + ((bRaw + jj * 2048 + kk * 32) ^ bX));
                b[2 * jj][0] = r0; b[2 * jj][1] = r1;
                b[2 * jj + 1][0] = r2; b[2 * jj + 1][1] = r3;
            }
#pragma unroll
            for (int i = 0; i < 4; i++)
#pragma unroll
                for (int j = 0; j < 4; j++)
                    MMA_F16(acc[i][j], a[i], b[j]);
        }
    }

    const int rr = lane >> 2;
    const int cc = (lane & 3) * 2;
#pragma unroll
    for (int i = 0; i < 4; i++) {
        const int m1 = wm + 16 * i + rr;
        const int m2 = m1 + 8;
        const int pk1 = s_tok[m1], pk2 = s_tok[m2];
        const float w1 = s_w[m1], w2 = s_w[m2];
        float* o1 = g_part + ((size_t)(pk1 & 1) * NTOK + (pk1 >> 1)) * HDIM + n0;
        float* o2 = g_part + ((size_t)(pk2 & 1) * NTOK + (pk2 >> 1)) * HDIM + n0;
#pragma unroll
        for (int j = 0; j < 4; j++) {
            const int n = wn + 8 * j + cc;
            if (pk1 >= 0) {
                float2 v = make_float2(w1 * (acc[i][j][0] + s_be[n]),
                                       w1 * (acc[i][j][1] + s_be[n + 1]));
                *(float2*)(o1 + n) = v;
            }
            if (pk2 >= 0) {
                float2 v = make_float2(w2 * (acc[i][j][2] + s_be[n]),
                                       w2 * (acc[i][j][3] + s_be[n + 1]));
                *(float2*)(o2 + n) = v;
            }
        }
    }
}

// ---------------------------------------------------------------------------
// Kernel 3: combine — out = part[slot0] + part[slot1]
// ---------------------------------------------------------------------------
__global__ void k_combine(float4* __restrict__ out, int n4) {
    int i = blockIdx.x * blockDim.x + threadIdx.x;
    if (i < n4) {
        float4 a = ((const float4*)g_part)[i];
        float4 b = ((const float4*)g_part)[(size_t)NTOK * HDIM / 4 + i];
        out[i] = make_float4(a.x + b.x, a.y + b.y, a.z + b.z, a.w + b.w);
    }
}

// ---------------------------------------------------------------------------
// Launch
// ---------------------------------------------------------------------------
extern "C" void kernel_launch(void* const* d_in, const int* in_sizes, int n_in,
                              void* d_out, int out_size) {
    const float* x  = (const float*)d_in[0];   // [N, D]
    const float* Wg = (const float*)d_in[1];   // [D, E]
    const float* bg = (const float*)d_in[2];   // [E]
    const float* We = (const float*)d_in[3];   // [E, D, H]
    const float* be = (const float*)d_in[4];   // [E, H]
    float* out = (float*)d_out;                // [N, H]
    (void)in_sizes; (void)n_in;

    cudaFuncSetAttribute(k_moe_gemm,
                         cudaFuncAttributeMaxDynamicSharedMemorySize, SMEM_BYTES);
    cudaFuncSetAttribute(k_gate,
                         cudaFuncAttributeMaxDynamicSharedMemorySize, GATE_SMEM);

    // 0) reset counters
    k_zero_cnt<<<1, 32>>>();

    // T) transpose + convert expert weights -> fp16 [e][h][d]
    {
        dim3 g(DDIM / 64, HDIM / 64, NEXP);
        dim3 b(32, 8);
        k_transpose<<<g, b>>>(We);
    }

    // 1) gating + x->fp16 (fused, Wg in dynamic smem)
    k_gate<<<NTOK / 32, 256, GATE_SMEM>>>(x, Wg, bg);

    // 2) grouped expert GEMM (mma.sync fp16, BM=128, 2 CTA/SM)
    {
        dim3 grid(HDIM / BN, NTOK / BM, NEXP);
        k_moe_gemm<<<grid, 256, SMEM_BYTES>>>(be);
    }

    // 3) combine slots
    {
        int n4 = NTOK * HDIM / 4;
        k_combine<<<(n4 + 255) / 256, 256>>>((float4*)out, n4);
    }
}